// round 4
// baseline (speedup 1.0000x reference)
#include <cuda_runtime.h>
#include <cstdint>

namespace {

constexpr int B_ = 8, H_ = 64, W_ = 64, C_ = 128, N_ = 9, F_ = 256;
constexpr int THREADS = 512;
constexpr int NCHUNK  = N_ * (C_ / 32);   // 36 chunks of K=32
constexpr int PADK    = 36;               // A tile k-stride (floats), conflict-free

// dynamic smem layout (floats)
constexpr int A_SZ    = 128 * PADK;       // 4608 floats per A buffer
constexpr int W_SZ    = 32 * 4 * 64;      // 8192 floats per W buffer (ft,kk,lane,2)
constexpr int A0_OFF  = 0;
constexpr int A1_OFF  = A_SZ;
constexpr int W0_OFF  = 2 * A_SZ;
constexpr int W1_OFF  = 2 * A_SZ + W_SZ;
constexpr int CRD_OFF = 2 * A_SZ + 2 * W_SZ;
constexpr int SMEM_FLOATS = CRD_OFF + 4 * N_ * 128;
constexpr int SMEM_BYTES  = SMEM_FLOATS * 4;   // 120832 B

// Faithful reproduction of reference (2,3,3)->(9,2) reshape order
__constant__ int c_iy[9] = {0, 0, 1, 2, 2, 1, 0, 2, 1};
__constant__ int c_ix[9] = {0, 1, 1, 2, 0, 2, 1, 0, 2};

// W fragment image: [n][cc][ft(32)][kk(4)][lane(32)][2] tf32 bits
__device__ uint32_t g_Wimg[N_ * 4 * W_SZ];

__device__ __forceinline__ uint32_t f2tf32(float v) {
    uint32_t u;
    asm("cvt.rna.tf32.f32 %0, %1;" : "=r"(u) : "f"(v));
    return u;
}
__device__ __forceinline__ uint32_t smem_u32(const void* p) {
    uint32_t a;
    asm("{ .reg .u64 t; cvta.to.shared.u64 t, %1; cvt.u32.u64 %0, t; }" : "=r"(a) : "l"(p));
    return a;
}
__device__ __forceinline__ void cp_async16(uint32_t dst, const void* src) {
    asm volatile("cp.async.ca.shared.global [%0], [%1], 16;" :: "r"(dst), "l"(src) : "memory");
}
__device__ __forceinline__ void cp_commit() {
    asm volatile("cp.async.commit_group;" ::: "memory");
}
__device__ __forceinline__ void cp_wait0() {
    asm volatile("cp.async.wait_group 0;" ::: "memory");
}
__device__ __forceinline__ void mma_tf32(float* c, const uint32_t* a, const uint32_t* b) {
    asm volatile(
        "mma.sync.aligned.m16n8k8.row.col.f32.tf32.tf32.f32 "
        "{%0,%1,%2,%3}, {%4,%5,%6,%7}, {%8,%9}, {%0,%1,%2,%3};"
        : "+f"(c[0]), "+f"(c[1]), "+f"(c[2]), "+f"(c[3])
        : "r"(a[0]), "r"(a[1]), "r"(a[2]), "r"(a[3]), "r"(b[0]), "r"(b[1]));
}

// ---------------- W fragment-image pre-kernel ----------------
__global__ void wimg_kernel(const float* __restrict__ Wt) {
    int idx = blockIdx.x * 256 + threadIdx.x;          // 0 .. 294911
    int j    = idx & 1;
    int lane = (idx >> 1) & 31;
    int kk   = (idx >> 6) & 3;
    int ft   = (idx >> 8) & 31;
    int cc   = (idx >> 13) & 3;
    int n    = idx >> 15;
    int f = ft * 8 + (lane >> 2);
    int c = cc * 32 + kk * 8 + (lane & 3) + 4 * j;
    g_Wimg[idx] = f2tf32(Wt[((size_t)n * C_ + c) * F_ + f]);
}

// ---------------- main fused kernel ----------------
__global__ __launch_bounds__(THREADS, 1)
void deform_mma_kernel(const float* __restrict__ x,
                       const float* __restrict__ offs,
                       const float* __restrict__ bias,
                       float* __restrict__ out) {
    extern __shared__ float smf[];
    uint32_t* A_buf[2] = { (uint32_t*)(smf + A0_OFF), (uint32_t*)(smf + A1_OFF) };
    uint32_t* W_buf[2] = { (uint32_t*)(smf + W0_OFF), (uint32_t*)(smf + W1_OFF) };
    int*   s_y0 = (int*)(smf + CRD_OFF);
    int*   s_x0 = s_y0 + N_ * 128;
    float* s_fy = (float*)(s_x0 + N_ * 128);
    float* s_fx = s_fy + N_ * 128;

    const uint32_t w_smem_u32[2] = { smem_u32(W_buf[0]), smem_u32(W_buf[1]) };

    const int tid  = threadIdx.x;
    const int wid  = tid >> 5;
    const int lane = tid & 31;
    const int wr   = wid >> 2;        // warp row (0..3): m base = wr*32
    const int wc   = wid & 3;         // warp col (0..3): f base = wc*64
    const int gq   = lane >> 2;       // groupID
    const int tq   = lane & 3;        // threadID in group

    const int blk = blockIdx.x;
    const int b   = blk >> 5;
    const int h0  = (blk & 31) * 2;
    const float* img = x + (size_t)b * H_ * W_ * C_;

    const int c4  = tid & 7;          // float4 index within 32-ch chunk
    const int pix = tid >> 3;         // 0..63

    // ---- precompute coordinates for all 9 taps ----
    for (int e = tid; e < N_ * 128; e += THREADS) {
        const int n  = e >> 7;
        const int lp = e & 127;
        const int hh = h0 + (lp >> 6);
        const int ww = lp & 63;
        const float* orow = offs + (((size_t)(b * H_ + hh) * W_ + ww) * (2 * N_));
        float cy = (float)(hh - 1 + c_iy[n]) + orow[2 * n];
        float cx = (float)(ww - 1 + c_ix[n]) + orow[2 * n + 1];
        cy = fminf(fmaxf(cy, 0.0f), 63.0f);
        cx = fminf(fmaxf(cx, 0.0f), 63.0f);
        float y0f = floorf(cy);
        float x0f = floorf(cx);
        s_y0[e] = (int)y0f;
        s_x0[e] = (int)x0f;
        s_fy[e] = cy - y0f;
        s_fx[e] = cx - x0f;
    }
    __syncthreads();

    float acc[2][8][4];
    #pragma unroll
    for (int mi = 0; mi < 2; mi++)
        #pragma unroll
        for (int ni = 0; ni < 8; ni++)
            #pragma unroll
            for (int r = 0; r < 4; r++) acc[mi][ni][r] = 0.0f;

    // ---- prologue: stage chunk 0 ----
    {
        // W(0) via cp.async
        const uint32_t* wsrc = g_Wimg;   // n=0, cc=0
        #pragma unroll
        for (int i = 0; i < 4; i++) {
            int o = i * THREADS + tid;
            cp_async16(w_smem_u32[0] + o * 16u, wsrc + o * 4);
        }
        cp_commit();
        // A(0): gather + lerp + STS
        const int c_off = c4 * 4;        // cc=0
        #pragma unroll
        for (int i = 0; i < 2; i++) {
            const int lp = pix + i * 64;
            const int y0 = s_y0[lp];
            const int x0 = s_x0[lp];
            const float fy = s_fy[lp];
            const float fx = s_fx[lp];
            const int y1 = min(y0 + 1, 63);
            const int x1 = min(x0 + 1, 63);
            float4 vlt = *(const float4*)(img + ((y0 * 64 + x0) << 7) + c_off);
            float4 vrt = *(const float4*)(img + ((y1 * 64 + x0) << 7) + c_off);
            float4 vlb = *(const float4*)(img + ((y0 * 64 + x1) << 7) + c_off);
            float4 vrb = *(const float4*)(img + ((y1 * 64 + x1) << 7) + c_off);
            float t0 = vlt.x + (vrt.x - vlt.x) * fy, b0 = vlb.x + (vrb.x - vlb.x) * fy;
            float t1 = vlt.y + (vrt.y - vlt.y) * fy, b1 = vlb.y + (vrb.y - vlb.y) * fy;
            float t2 = vlt.z + (vrt.z - vlt.z) * fy, b2 = vlb.z + (vrb.z - vlb.z) * fy;
            float t3 = vlt.w + (vrt.w - vlt.w) * fy, b3 = vlb.w + (vrb.w - vlb.w) * fy;
            uint4 v;
            v.x = f2tf32(t0 + (b0 - t0) * fx);
            v.y = f2tf32(t1 + (b1 - t1) * fx);
            v.z = f2tf32(t2 + (b2 - t2) * fx);
            v.w = f2tf32(t3 + (b3 - t3) * fx);
            *(uint4*)(A_buf[0] + lp * PADK + c4 * 4) = v;
        }
    }

    // ---- main pipelined loop ----
    for (int it = 0; it < NCHUNK; it++) {
        cp_wait0();
        __syncthreads();

        const int buf  = it & 1;
        const int nbuf = buf ^ 1;
        const bool more = (it + 1 < NCHUNK);

        float4 v[2][4];
        float pfy[2], pfx[2];

        if (more) {
            const int n2  = (it + 1) >> 2;
            const int cc2 = (it + 1) & 3;
            // W(it+1) via cp.async (zero registers held)
            const uint32_t* wsrc = g_Wimg + (size_t)(n2 * 4 + cc2) * W_SZ;
            #pragma unroll
            for (int i = 0; i < 4; i++) {
                int o = i * THREADS + tid;
                cp_async16(w_smem_u32[nbuf] + o * 16u, wsrc + o * 4);
            }
            cp_commit();
            // A(it+1): issue all 8 LDG.128 now; lerp after MMA
            const int c_off = cc2 * 32 + c4 * 4;
            #pragma unroll
            for (int i = 0; i < 2; i++) {
                const int lp = pix + i * 64;
                const int e  = n2 * 128 + lp;
                const int y0 = s_y0[e];
                const int x0 = s_x0[e];
                pfy[i] = s_fy[e];
                pfx[i] = s_fx[e];
                const int y1 = min(y0 + 1, 63);
                const int x1 = min(x0 + 1, 63);
                v[i][0] = *(const float4*)(img + ((y0 * 64 + x0) << 7) + c_off);
                v[i][1] = *(const float4*)(img + ((y1 * 64 + x0) << 7) + c_off);
                v[i][2] = *(const float4*)(img + ((y0 * 64 + x1) << 7) + c_off);
                v[i][3] = *(const float4*)(img + ((y1 * 64 + x1) << 7) + c_off);
            }
        }

        // ---- MMA(it) ----
        {
            const uint32_t* A_s = A_buf[buf];
            const uint32_t* W_s = W_buf[buf];
            #pragma unroll
            for (int kk = 0; kk < 4; kk++) {
                const int kb = kk * 8 + tq;
                uint32_t a[2][4];
                #pragma unroll
                for (int mi = 0; mi < 2; mi++) {
                    const int r0 = wr * 32 + mi * 16 + gq;
                    a[mi][0] = A_s[r0 * PADK + kb];
                    a[mi][1] = A_s[(r0 + 8) * PADK + kb];
                    a[mi][2] = A_s[r0 * PADK + kb + 4];
                    a[mi][3] = A_s[(r0 + 8) * PADK + kb + 4];
                }
                #pragma unroll
                for (int ni = 0; ni < 8; ni++) {
                    const int ftl = wc * 8 + ni;
                    uint2 bv = *(const uint2*)(W_s + (ftl * 4 + kk) * 64 + lane * 2);
                    uint32_t bb[2] = { bv.x, bv.y };
                    mma_tf32(acc[0][ni], a[0], bb);
                    mma_tf32(acc[1][ni], a[1], bb);
                }
            }
        }

        // ---- finish A(it+1): lerp + cvt + STS ----
        if (more) {
            #pragma unroll
            for (int i = 0; i < 2; i++) {
                const int lp = pix + i * 64;
                const float fy = pfy[i], fx = pfx[i];
                float t0 = v[i][0].x + (v[i][1].x - v[i][0].x) * fy;
                float b0 = v[i][2].x + (v[i][3].x - v[i][2].x) * fy;
                float t1 = v[i][0].y + (v[i][1].y - v[i][0].y) * fy;
                float b1 = v[i][2].y + (v[i][3].y - v[i][2].y) * fy;
                float t2 = v[i][0].z + (v[i][1].z - v[i][0].z) * fy;
                float b2 = v[i][2].z + (v[i][3].z - v[i][2].z) * fy;
                float t3 = v[i][0].w + (v[i][1].w - v[i][0].w) * fy;
                float b3 = v[i][2].w + (v[i][3].w - v[i][2].w) * fy;
                uint4 o;
                o.x = f2tf32(t0 + (b0 - t0) * fx);
                o.y = f2tf32(t1 + (b1 - t1) * fx);
                o.z = f2tf32(t2 + (b2 - t2) * fx);
                o.w = f2tf32(t3 + (b3 - t3) * fx);
                *(uint4*)(A_buf[nbuf] + lp * PADK + c4 * 4) = o;
            }
        }
    }

    // ---- epilogue: add bias, store ----
    #pragma unroll
    for (int mi = 0; mi < 2; mi++) {
        const int row0 = wr * 32 + mi * 16 + gq;
        float* o0 = out + ((size_t)blk * 128 + row0) * F_;
        float* o1 = o0 + 8 * F_;
        #pragma unroll
        for (int ni = 0; ni < 8; ni++) {
            const int f = wc * 64 + ni * 8 + tq * 2;
            const float2 bb = *(const float2*)(bias + f);
            float2 r0, r1;
            r0.x = acc[mi][ni][0] + bb.x;
            r0.y = acc[mi][ni][1] + bb.y;
            r1.x = acc[mi][ni][2] + bb.x;
            r1.y = acc[mi][ni][3] + bb.y;
            *(float2*)(o0 + f) = r0;
            *(float2*)(o1 + f) = r1;
        }
    }
}

}  // namespace

extern "C" void kernel_launch(void* const* d_in, const int* in_sizes, int n_in,
                              void* d_out, int out_size) {
    (void)in_sizes; (void)n_in; (void)out_size;
    const float* x    = (const float*)d_in[0];   // (8,64,64,128)
    const float* offs = (const float*)d_in[1];   // (8,64,64,18)
    const float* Wt   = (const float*)d_in[2];   // (9,128,256)
    const float* bias = (const float*)d_in[3];   // (256,)
    float* out = (float*)d_out;                  // (8,64,64,256)

    cudaFuncSetAttribute(deform_mma_kernel,
                         cudaFuncAttributeMaxDynamicSharedMemorySize, SMEM_BYTES);

    wimg_kernel<<<(N_ * 4 * W_SZ) / 256, 256>>>(Wt);
    deform_mma_kernel<<<256, THREADS, SMEM_BYTES>>>(x, offs, bias, out);
}

// round 5
// speedup vs baseline: 1.4402x; 1.4402x over previous
#include <cuda_runtime.h>
#include <cuda_fp16.h>
#include <cstdint>

namespace {

constexpr int B_ = 8, H_ = 64, W_ = 64, C_ = 128, N_ = 9, F_ = 256;
constexpr int THREADS = 512;
constexpr int NCHUNK  = N_ * (C_ / 32);   // 36 chunks of K=32
constexpr int PADP    = 20;               // A stride in b32 pairs (16 data + 4 pad)

// dynamic smem layout (b32 units)
constexpr int A_SZ    = 128 * PADP;       // 2560 words per A buffer
constexpr int W_SZ    = 32 * 2 * 32 * 2;  // 4096 words per W buffer [ft][ks][lane][2]
constexpr int A0_OFF  = 0;
constexpr int A1_OFF  = A_SZ;
constexpr int W0_OFF  = 2 * A_SZ;
constexpr int W1_OFF  = 2 * A_SZ + W_SZ;
constexpr int CRD_OFF = 2 * A_SZ + 2 * W_SZ;
constexpr int SMEM_WORDS = CRD_OFF + 4 * N_ * 128;
constexpr int SMEM_BYTES = SMEM_WORDS * 4;    // 71680 B

// Faithful reproduction of reference (2,3,3)->(9,2) reshape order
__constant__ int c_iy[9] = {0, 0, 1, 2, 2, 1, 0, 2, 1};
__constant__ int c_ix[9] = {0, 1, 1, 2, 0, 2, 1, 0, 2};

// W fragment image (fp16 pairs): [n][cc][ft(32)][ks(2)][lane(32)][j(2)]
__device__ uint32_t g_Wimg[N_ * 4 * W_SZ];

__device__ __forceinline__ uint32_t pack2(float a, float b) {
    __half2 h = __floats2half2_rn(a, b);   // .x = a (low), .y = b (high)
    return *reinterpret_cast<uint32_t*>(&h);
}
__device__ __forceinline__ uint32_t smem_u32(const void* p) {
    uint32_t a;
    asm("{ .reg .u64 t; cvta.to.shared.u64 t, %1; cvt.u32.u64 %0, t; }" : "=r"(a) : "l"(p));
    return a;
}
__device__ __forceinline__ void cp_async16(uint32_t dst, const void* src) {
    asm volatile("cp.async.ca.shared.global [%0], [%1], 16;" :: "r"(dst), "l"(src) : "memory");
}
__device__ __forceinline__ void cp_commit() {
    asm volatile("cp.async.commit_group;" ::: "memory");
}
__device__ __forceinline__ void cp_wait0() {
    asm volatile("cp.async.wait_group 0;" ::: "memory");
}
__device__ __forceinline__ void mma_f16(float* c, const uint32_t* a, uint32_t b0, uint32_t b1) {
    asm volatile(
        "mma.sync.aligned.m16n8k16.row.col.f32.f16.f16.f32 "
        "{%0,%1,%2,%3}, {%4,%5,%6,%7}, {%8,%9}, {%0,%1,%2,%3};"
        : "+f"(c[0]), "+f"(c[1]), "+f"(c[2]), "+f"(c[3])
        : "r"(a[0]), "r"(a[1]), "r"(a[2]), "r"(a[3]), "r"(b0), "r"(b1));
}

// ---------------- W fragment-image pre-kernel (fp16) ----------------
__global__ void wimg_kernel(const float* __restrict__ Wt) {
    int idx = blockIdx.x * 256 + threadIdx.x;   // 0 .. N_*4*W_SZ-1
    int j    = idx & 1;
    int lane = (idx >> 1) & 31;
    int ks   = (idx >> 6) & 1;
    int ft   = (idx >> 7) & 31;
    int cc   = (idx >> 12) & 3;
    int n    = idx >> 14;
    int gq = lane >> 2, tq = lane & 3;
    int f  = ft * 8 + gq;
    int c0 = cc * 32 + ks * 16 + j * 8 + tq * 2;
    float w0 = Wt[((size_t)n * C_ + c0) * F_ + f];
    float w1 = Wt[((size_t)n * C_ + c0 + 1) * F_ + f];
    g_Wimg[idx] = pack2(w0, w1);
}

// ---------------- main fused kernel ----------------
__global__ __launch_bounds__(THREADS, 1)
void deform_mma_kernel(const float* __restrict__ x,
                       const float* __restrict__ offs,
                       const float* __restrict__ bias,
                       float* __restrict__ out) {
    extern __shared__ float smf[];
    uint32_t* A_buf[2] = { (uint32_t*)smf + A0_OFF, (uint32_t*)smf + A1_OFF };
    uint32_t* W_buf[2] = { (uint32_t*)smf + W0_OFF, (uint32_t*)smf + W1_OFF };
    int*   s_y0 = (int*)smf + CRD_OFF;
    int*   s_x0 = s_y0 + N_ * 128;
    float* s_fy = (float*)(s_x0 + N_ * 128);
    float* s_fx = s_fy + N_ * 128;

    const uint32_t w_smem_u32[2] = { smem_u32(W_buf[0]), smem_u32(W_buf[1]) };

    const int tid  = threadIdx.x;
    const int wid  = tid >> 5;
    const int lane = tid & 31;
    const int wr   = wid >> 2;        // warp row (0..3): m base = wr*32
    const int wc   = wid & 3;         // warp col (0..3): f base = wc*64
    const int gq   = lane >> 2;
    const int tq   = lane & 3;

    const int blk = blockIdx.x;
    const int b   = blk >> 5;
    const int h0  = (blk & 31) * 2;
    const float* img = x + (size_t)b * H_ * W_ * C_;

    const int c4  = tid & 7;          // float4 index within 32-ch chunk
    const int pix = tid >> 3;         // 0..63

    // ---- precompute coordinates for all 9 taps ----
    for (int e = tid; e < N_ * 128; e += THREADS) {
        const int n  = e >> 7;
        const int lp = e & 127;
        const int hh = h0 + (lp >> 6);
        const int ww = lp & 63;
        const float* orow = offs + (((size_t)(b * H_ + hh) * W_ + ww) * (2 * N_));
        float cy = (float)(hh - 1 + c_iy[n]) + orow[2 * n];
        float cx = (float)(ww - 1 + c_ix[n]) + orow[2 * n + 1];
        cy = fminf(fmaxf(cy, 0.0f), 63.0f);
        cx = fminf(fmaxf(cx, 0.0f), 63.0f);
        float y0f = floorf(cy);
        float x0f = floorf(cx);
        s_y0[e] = (int)y0f;
        s_x0[e] = (int)x0f;
        s_fy[e] = cy - y0f;
        s_fx[e] = cx - x0f;
    }
    __syncthreads();

    float acc[2][8][4];
    #pragma unroll
    for (int mi = 0; mi < 2; mi++)
        #pragma unroll
        for (int ni = 0; ni < 8; ni++)
            #pragma unroll
            for (int r = 0; r < 4; r++) acc[mi][ni][r] = 0.0f;

    // ---- prologue: stage chunk 0 ----
    {
        const uint32_t* wsrc = g_Wimg;   // n=0, cc=0
        #pragma unroll
        for (int i = 0; i < 2; i++) {
            int o = i * THREADS + tid;
            cp_async16(w_smem_u32[0] + o * 16u, wsrc + o * 4);
        }
        cp_commit();
        const int c_off = c4 * 4;        // cc=0
        #pragma unroll
        for (int i = 0; i < 2; i++) {
            const int lp = pix + i * 64;
            const int y0 = s_y0[lp];
            const int x0 = s_x0[lp];
            const float fy = s_fy[lp];
            const float fx = s_fx[lp];
            const int y1 = min(y0 + 1, 63);
            const int x1 = min(x0 + 1, 63);
            float4 vlt = *(const float4*)(img + ((y0 * 64 + x0) << 7) + c_off);
            float4 vrt = *(const float4*)(img + ((y1 * 64 + x0) << 7) + c_off);
            float4 vlb = *(const float4*)(img + ((y0 * 64 + x1) << 7) + c_off);
            float4 vrb = *(const float4*)(img + ((y1 * 64 + x1) << 7) + c_off);
            float t0 = vlt.x + (vrt.x - vlt.x) * fy, b0 = vlb.x + (vrb.x - vlb.x) * fy;
            float t1 = vlt.y + (vrt.y - vlt.y) * fy, b1 = vlb.y + (vrb.y - vlb.y) * fy;
            float t2 = vlt.z + (vrt.z - vlt.z) * fy, b2 = vlb.z + (vrb.z - vlb.z) * fy;
            float t3 = vlt.w + (vrt.w - vlt.w) * fy, b3 = vlb.w + (vrb.w - vlb.w) * fy;
            uint2 v;
            v.x = pack2(t0 + (b0 - t0) * fx, t1 + (b1 - t1) * fx);
            v.y = pack2(t2 + (b2 - t2) * fx, t3 + (b3 - t3) * fx);
            *(uint2*)(A_buf[0] + lp * PADP + c4 * 2) = v;
        }
    }

    // ---- main pipelined loop ----
    for (int it = 0; it < NCHUNK; it++) {
        cp_wait0();
        __syncthreads();

        const int buf  = it & 1;
        const int nbuf = buf ^ 1;
        const bool more = (it + 1 < NCHUNK);

        float4 v[2][4];
        float pfy[2], pfx[2];

        if (more) {
            const int n2  = (it + 1) >> 2;
            const int cc2 = (it + 1) & 3;
            const uint32_t* wsrc = g_Wimg + (size_t)(n2 * 4 + cc2) * W_SZ;
            #pragma unroll
            for (int i = 0; i < 2; i++) {
                int o = i * THREADS + tid;
                cp_async16(w_smem_u32[nbuf] + o * 16u, wsrc + o * 4);
            }
            cp_commit();
            const int c_off = cc2 * 32 + c4 * 4;
            #pragma unroll
            for (int i = 0; i < 2; i++) {
                const int lp = pix + i * 64;
                const int e  = n2 * 128 + lp;
                const int y0 = s_y0[e];
                const int x0 = s_x0[e];
                pfy[i] = s_fy[e];
                pfx[i] = s_fx[e];
                const int y1 = min(y0 + 1, 63);
                const int x1 = min(x0 + 1, 63);
                v[i][0] = *(const float4*)(img + ((y0 * 64 + x0) << 7) + c_off);
                v[i][1] = *(const float4*)(img + ((y1 * 64 + x0) << 7) + c_off);
                v[i][2] = *(const float4*)(img + ((y0 * 64 + x1) << 7) + c_off);
                v[i][3] = *(const float4*)(img + ((y1 * 64 + x1) << 7) + c_off);
            }
        }

        // ---- MMA(it): 2 k-steps of m16n8k16 fp16 ----
        {
            const uint32_t* A_s = A_buf[buf];
            const uint32_t* W_s = W_buf[buf];
            #pragma unroll
            for (int ks = 0; ks < 2; ks++) {
                const int kp = ks * 8 + tq;
                uint32_t a[2][4];
                #pragma unroll
                for (int mi = 0; mi < 2; mi++) {
                    const int r0 = wr * 32 + mi * 16 + gq;
                    a[mi][0] = A_s[r0 * PADP + kp];
                    a[mi][1] = A_s[(r0 + 8) * PADP + kp];
                    a[mi][2] = A_s[r0 * PADP + kp + 4];
                    a[mi][3] = A_s[(r0 + 8) * PADP + kp + 4];
                }
                #pragma unroll
                for (int ni = 0; ni < 8; ni++) {
                    const int ftl = wc * 8 + ni;
                    uint2 bv = *(const uint2*)(W_s + ((ftl * 2 + ks) * 32 + lane) * 2);
                    mma_f16(acc[0][ni], a[0], bv.x, bv.y);
                    mma_f16(acc[1][ni], a[1], bv.x, bv.y);
                }
            }
        }

        // ---- finish A(it+1): lerp + pack + STS ----
        if (more) {
            #pragma unroll
            for (int i = 0; i < 2; i++) {
                const int lp = pix + i * 64;
                const float fy = pfy[i], fx = pfx[i];
                float t0 = v[i][0].x + (v[i][1].x - v[i][0].x) * fy;
                float b0 = v[i][2].x + (v[i][3].x - v[i][2].x) * fy;
                float t1 = v[i][0].y + (v[i][1].y - v[i][0].y) * fy;
                float b1 = v[i][2].y + (v[i][3].y - v[i][2].y) * fy;
                float t2 = v[i][0].z + (v[i][1].z - v[i][0].z) * fy;
                float b2 = v[i][2].z + (v[i][3].z - v[i][2].z) * fy;
                float t3 = v[i][0].w + (v[i][1].w - v[i][0].w) * fy;
                float b3 = v[i][2].w + (v[i][3].w - v[i][2].w) * fy;
                uint2 o;
                o.x = pack2(t0 + (b0 - t0) * fx, t1 + (b1 - t1) * fx);
                o.y = pack2(t2 + (b2 - t2) * fx, t3 + (b3 - t3) * fx);
                *(uint2*)(A_buf[nbuf] + lp * PADP + c4 * 2) = o;
            }
        }
    }

    // ---- epilogue: add bias, store ----
    #pragma unroll
    for (int mi = 0; mi < 2; mi++) {
        const int row0 = wr * 32 + mi * 16 + gq;
        float* o0 = out + ((size_t)blk * 128 + row0) * F_;
        float* o1 = o0 + 8 * F_;
        #pragma unroll
        for (int ni = 0; ni < 8; ni++) {
            const int f = wc * 64 + ni * 8 + tq * 2;
            const float2 bb = *(const float2*)(bias + f);
            float2 r0, r1;
            r0.x = acc[mi][ni][0] + bb.x;
            r0.y = acc[mi][ni][1] + bb.y;
            r1.x = acc[mi][ni][2] + bb.x;
            r1.y = acc[mi][ni][3] + bb.y;
            *(float2*)(o0 + f) = r0;
            *(float2*)(o1 + f) = r1;
        }
    }
}

}  // namespace

extern "C" void kernel_launch(void* const* d_in, const int* in_sizes, int n_in,
                              void* d_out, int out_size) {
    (void)in_sizes; (void)n_in; (void)out_size;
    const float* x    = (const float*)d_in[0];   // (8,64,64,128)
    const float* offs = (const float*)d_in[1];   // (8,64,64,18)
    const float* Wt   = (const float*)d_in[2];   // (9,128,256)
    const float* bias = (const float*)d_in[3];   // (256,)
    float* out = (float*)d_out;                  // (8,64,64,256)

    cudaFuncSetAttribute(deform_mma_kernel,
                         cudaFuncAttributeMaxDynamicSharedMemorySize, SMEM_BYTES);

    wimg_kernel<<<(N_ * 4 * W_SZ) / 256, 256>>>(Wt);
    deform_mma_kernel<<<256, THREADS, SMEM_BYTES>>>(x, offs, bias, out);
}